// round 2
// baseline (speedup 1.0000x reference)
#include <cuda_runtime.h>

#define P  4096
#define M  64
#define BI 128          // i-rows per CTA
#define BJ 128          // j-cols per CTA (split-K chunk)
#define PADJ 132        // BJ + 4 floats padding (16B-aligned rows, conflict-free)
#define NT 256

// Scratch (device globals — no allocations allowed)
__device__ float g_Dacc[P * M];
__device__ int   g_counts[P];
__device__ int   g_total;

// Packed f32x2 FMA (sm_10x FFMA2) — acc.{lo,hi} += a.{lo,hi} * b.{lo,hi}
__device__ __forceinline__ void ffma2(unsigned long long& acc,
                                      unsigned long long a,
                                      unsigned long long b) {
    asm("fma.rn.f32x2 %0, %1, %2, %0;" : "+l"(acc) : "l"(a), "l"(b));
}

__global__ void zero_kernel() {
    int idx = blockIdx.x * NT + threadIdx.x;
    if (idx < P * M) g_Dacc[idx] = 0.0f;
    if (idx < P)     g_counts[idx] = 0;
    if (idx == 0)    g_total = 0;
}

extern __shared__ float smem[];

__global__ __launch_bounds__(NT, 2)
void social_main(const float* __restrict__ hidden,
                 const int* __restrict__ nei) {
    float* sh_mask = smem;                 // [BI][PADJ] fp32 {0,1}
    float* sh_hT   = smem + BI * PADJ;     // [M][PADJ]  hidden transposed (j contiguous)

    const int tid  = threadIdx.x;
    const int lane = tid & 31;
    const int wid  = tid >> 5;
    const int i0   = blockIdx.y * BI;
    const int j0   = blockIdx.x * BJ;

    // ---- Phase 1: stage hidden chunk transposed: sh_hT[m][j] = hidden[j0+j][m]
    for (int idx = tid; idx < BJ * M; idx += NT) {
        int j = idx >> 6;       // M == 64
        int m = idx & 63;
        sh_hT[m * PADJ + j] = hidden[(size_t)(j0 + j) * M + m];
    }

    // ---- Phase 2: int32 mask -> fp32 {0,1} in smem, plus per-row neighbor counts
    // Each warp handles 16 rows; per row, 32 lanes x int4 = 128 j-values (512B coalesced).
    #pragma unroll
    for (int rr = 0; rr < BI / 8; ++rr) {
        int r = wid * (BI / 8) + rr;
        const int4* nrow = reinterpret_cast<const int4*>(
            nei + (size_t)(i0 + r) * P + j0);
        int4 v = nrow[lane];
        float4 f;
        f.x = (v.x > 0) ? 1.0f : 0.0f;
        f.y = (v.y > 0) ? 1.0f : 0.0f;
        f.z = (v.z > 0) ? 1.0f : 0.0f;
        f.w = (v.w > 0) ? 1.0f : 0.0f;
        *reinterpret_cast<float4*>(&sh_mask[r * PADJ + lane * 4]) = f;   // 16B-aligned
        int cnt = (v.x > 0) + (v.y > 0) + (v.z > 0) + (v.w > 0);
        int rowcnt = __reduce_add_sync(0xffffffffu, cnt);
        if (lane == 0 && rowcnt) {
            atomicAdd(&g_counts[i0 + r], rowcnt);
            atomicAdd(&g_total, rowcnt);
        }
    }
    __syncthreads();

    // ---- Phase 3: masked accumulation.
    // Warp wid owns m in [wid*8, wid*8+8); lane owns rows {lane, lane+32, lane+64, lane+96}.
    // Accumulators pair over j (f32x2): acc[r][c] = (sum over even j, sum over odd j).
    const int m0 = wid * 8;
    unsigned long long acc[4][8];
    #pragma unroll
    for (int r = 0; r < 4; ++r)
        #pragma unroll
        for (int c = 0; c < 8; ++c) acc[r][c] = 0ull;

    for (int j4 = 0; j4 < BJ; j4 += 4) {
        unsigned long long mq[4][2];
        #pragma unroll
        for (int r = 0; r < 4; ++r) {
            const float* mp = &sh_mask[(lane + 32 * r) * PADJ + j4];
            double2 q = *reinterpret_cast<const double2*>(mp);   // LDS.128, conflict-free
            mq[r][0] = __double_as_longlong(q.x);
            mq[r][1] = __double_as_longlong(q.y);
        }
        #pragma unroll
        for (int c = 0; c < 8; ++c) {
            const float* hp = &sh_hT[(m0 + c) * PADJ + j4];
            double2 hq = *reinterpret_cast<const double2*>(hp);  // uniform -> broadcast
            unsigned long long h01 = __double_as_longlong(hq.x);
            unsigned long long h23 = __double_as_longlong(hq.y);
            #pragma unroll
            for (int r = 0; r < 4; ++r) {
                ffma2(acc[r][c], mq[r][0], h01);
                ffma2(acc[r][c], mq[r][1], h23);
            }
        }
    }

    // ---- Epilogue: fold j-pairs, split-K combine via fp32 atomics
    #pragma unroll
    for (int r = 0; r < 4; ++r) {
        int gi = i0 + lane + 32 * r;
        #pragma unroll
        for (int c = 0; c < 8; ++c) {
            float lo = __int_as_float((unsigned)(acc[r][c] & 0xffffffffull));
            float hi = __int_as_float((unsigned)(acc[r][c] >> 32));
            atomicAdd(&g_Dacc[(size_t)gi * M + m0 + c], lo + hi);
        }
    }
}

__global__ void finalize_kernel(const float* __restrict__ hidden,
                                float* __restrict__ out) {
    int idx = blockIdx.x * NT + threadIdx.x;
    if (idx >= P * M) return;
    if (g_total > 0) {
        int i = idx >> 6;
        float c = (float)g_counts[i];
        // softmax with max-shift: neighbors -> exp(0)=1, others -> exp(-1e-6 - 1)
        float denom = c + ((float)P - c) * expf(-1.000001f);
        out[idx] = g_Dacc[idx] / denom;
    } else {
        out[idx] = hidden[idx];
    }
}

extern "C" void kernel_launch(void* const* d_in, const int* in_sizes, int n_in,
                              void* d_out, int out_size) {
    const float* hidden = (const float*)d_in[0];
    // d_in[1] (corr_index) is unused by the reference math — never touched.
    const int*   nei    = (const int*)d_in[2];   // JAX x64-disabled: int64 -> int32
    float*       out    = (float*)d_out;

    const size_t smem_bytes = (size_t)(BI + M) * PADJ * sizeof(float);  // 101,376 B
    cudaFuncSetAttribute(social_main,
                         cudaFuncAttributeMaxDynamicSharedMemorySize,
                         (int)smem_bytes);

    zero_kernel<<<(P * M + NT - 1) / NT, NT>>>();

    dim3 grid(P / BJ, P / BI);   // (32 j-chunks, 32 i-tiles) = 1024 CTAs
    social_main<<<grid, NT, smem_bytes>>>(hidden, nei);

    finalize_kernel<<<(P * M + NT - 1) / NT, NT>>>(hidden, out);
}

// round 5
// speedup vs baseline: 4.0340x; 4.0340x over previous
#include <cuda_runtime.h>
#include <cuda_bf16.h>
#include <cstdint>

#define P       4096
#define MOUT    64
#define NB      128              // GEMM N: interleaved hi/lo (n=2m hi, n=2m+1 lo)
#define ITILE   128              // i-rows per CTA
#define SPLITS  4
#define KSPLIT  (P / SPLITS)     // 1024
#define KC      64               // k per chunk
#define NCHUNK  (KSPLIT / KC)    // 16
#define NT      256

// ---------------- device scratch (no allocations allowed) ----------------
__device__ __nv_bfloat16 g_B[NB * P];                 // [n][k], k contiguous
__device__ float         g_Dpart[SPLITS][P][MOUT];    // split-K partials (4 MB)
__device__ int           g_counts[P];
__device__ int           g_total;

// ---------------- helpers ----------------
__device__ __forceinline__ uint32_t smem_u32(const void* p) {
    uint32_t a;
    asm("{ .reg .u64 t; cvta.to.shared.u64 t, %1; cvt.u32.u64 %0, t; }" : "=r"(a) : "l"(p));
    return a;
}
// Row = 64 bf16 = 128 B. Swizzle 16B chunks within a row: chunk' = chunk ^ (row&7).
// Self-consistent between STS and ldmatrix (both call sw()); conflict-free ldmatrix phases.
__device__ __forceinline__ uint32_t sw(int row, int kbyte) {
    return (uint32_t)(row * 128) + (uint32_t)(kbyte ^ ((row & 7) << 4));
}
// Explicit shared-space 8B store — avoids any generic-pointer UB; pairs with ldmatrix's
// shared-window u32 addressing (same sbase-relative space).
__device__ __forceinline__ void sts64(uint32_t addr, uint32_t x, uint32_t y) {
    asm volatile("st.shared.v2.b32 [%0], {%1, %2};" :: "r"(addr), "r"(x), "r"(y) : "memory");
}
__device__ __forceinline__ void ldsm4(uint32_t* r, uint32_t addr) {
    asm volatile("ldmatrix.sync.aligned.m8n8.x4.shared.b16 {%0,%1,%2,%3}, [%4];"
                 : "=r"(r[0]), "=r"(r[1]), "=r"(r[2]), "=r"(r[3]) : "r"(addr));
}
__device__ __forceinline__ void mma16816(float* c, const uint32_t* a, const uint32_t* b) {
    asm volatile("mma.sync.aligned.m16n8k16.row.col.f32.bf16.bf16.f32 "
                 "{%0,%1,%2,%3}, {%4,%5,%6,%7}, {%8,%9}, {%0,%1,%2,%3};"
                 : "+f"(c[0]), "+f"(c[1]), "+f"(c[2]), "+f"(c[3])
                 : "r"(a[0]), "r"(a[1]), "r"(a[2]), "r"(a[3]), "r"(b[0]), "r"(b[1]));
}

// ---------------- kernel 1: build B (hi/lo interleaved), zero counts ----------------
__global__ void prep_kernel(const float* __restrict__ hidden) {
    int k = blockIdx.x * NT + threadIdx.x;            // 16 CTAs x 256 = 4096
    g_counts[k] = 0;
    if (k == 0) g_total = 0;
    const float4* src = reinterpret_cast<const float4*>(hidden + (size_t)k * MOUT);
    #pragma unroll
    for (int q = 0; q < MOUT / 4; ++q) {
        float4 v = src[q];
        float vv[4] = {v.x, v.y, v.z, v.w};
        #pragma unroll
        for (int e = 0; e < 4; ++e) {
            int m = q * 4 + e;
            __nv_bfloat16 hi = __float2bfloat16(vv[e]);
            __nv_bfloat16 lo = __float2bfloat16(vv[e] - __bfloat162float(hi));
            g_B[(size_t)(2 * m)     * P + k] = hi;    // coalesced along k
            g_B[(size_t)(2 * m + 1) * P + k] = lo;
        }
    }
}

// ---------------- kernel 2: mma.sync GEMM, mask converted on the fly ----------------
extern __shared__ __align__(16) char smem[];   // [A0 16K][A1 16K][B0 16K][B1 16K]

__global__ __launch_bounds__(NT)
void gemm_kernel(const int* __restrict__ nei) {
    const int tid    = threadIdx.x;
    const int lane   = tid & 31;
    const int w      = tid >> 5;
    const int warp_m = w & 3;        // i-offset = warp_m*32
    const int warp_n = w >> 2;       // n-offset = warp_n*64
    const int split  = blockIdx.x;
    const int i0     = blockIdx.y * ITILE;
    const int k0base = split * KSPLIT;

    const uint32_t sbase = smem_u32(smem);
    const uint32_t sA[2] = {sbase,           sbase + 16384};
    const uint32_t sB[2] = {sbase + 32768,   sbase + 49152};

    // load mapping: thread owns rows r_t + 16*s (s=0..7), k-slice kl..kl+3
    const int r_t = tid >> 4;            // 0..15
    const int kl  = (tid & 15) * 4;      // element index within chunk

    float acc[2][8][4];
    #pragma unroll
    for (int a = 0; a < 2; ++a)
        #pragma unroll
        for (int b = 0; b < 8; ++b)
            #pragma unroll
            for (int c = 0; c < 4; ++c) acc[a][b][c] = 0.0f;
    int cnt[8];
    #pragma unroll
    for (int s = 0; s < 8; ++s) cnt[s] = 0;

    int4  va[8];
    uint2 vb[8];

    auto load_chunk = [&](int c) {
        const int k0 = k0base + c * KC;
        #pragma unroll
        for (int s = 0; s < 8; ++s) {
            int row = r_t + 16 * s;
            va[s] = *reinterpret_cast<const int4*>(nei + (size_t)(i0 + row) * P + k0 + kl);
            vb[s] = *reinterpret_cast<const uint2*>(g_B + (size_t)row * P + k0 + kl);
        }
    };
    auto sts_chunk = [&](int b) {
        #pragma unroll
        for (int s = 0; s < 8; ++s) {
            int row = r_t + 16 * s;
            uint32_t e0 = (va[s].x > 0) ? 0x3F80u : 0u;
            uint32_t e1 = (va[s].y > 0) ? 0x3F80u : 0u;
            uint32_t e2 = (va[s].z > 0) ? 0x3F80u : 0u;
            uint32_t e3 = (va[s].w > 0) ? 0x3F80u : 0u;
            cnt[s] += (va[s].x > 0) + (va[s].y > 0) + (va[s].z > 0) + (va[s].w > 0);
            uint32_t off = sw(row, kl * 2);              // 8B-aligned
            sts64(sA[b] + off, e0 | (e1 << 16), e2 | (e3 << 16));
            sts64(sB[b] + off, vb[s].x, vb[s].y);
        }
    };

    // ---- software pipeline: LDG(c+1) -> MMA(c) -> STS(c+1) -> sync
    load_chunk(0);
    sts_chunk(0);
    __syncthreads();

    #pragma unroll 1
    for (int c = 0; c < NCHUNK; ++c) {
        const int b = c & 1;
        if (c + 1 < NCHUNK) load_chunk(c + 1);

        #pragma unroll
        for (int k16 = 0; k16 < KC / 16; ++k16) {
            uint32_t afr[2][4];
            #pragma unroll
            for (int mt = 0; mt < 2; ++mt) {
                int row = warp_m * 32 + mt * 16 + (lane & 15);
                int kb  = k16 * 32 + ((lane >> 4) << 4);
                ldsm4(afr[mt], sA[b] + sw(row, kb));
            }
            uint32_t bfr[4][4];
            #pragma unroll
            for (int g = 0; g < 4; ++g) {
                int row = warp_n * 64 + g * 16 + (lane & 7) + ((lane >> 4) << 3);
                int kb  = k16 * 32 + (((lane >> 3) & 1) << 4);
                ldsm4(bfr[g], sB[b] + sw(row, kb));
            }
            #pragma unroll
            for (int mt = 0; mt < 2; ++mt)
                #pragma unroll
                for (int g = 0; g < 4; ++g) {
                    mma16816(acc[mt][2 * g],     afr[mt], &bfr[g][0]);  // n tile A
                    mma16816(acc[mt][2 * g + 1], afr[mt], &bfr[g][2]);  // n tile B (+8)
                }
        }

        if (c + 1 < NCHUNK) sts_chunk((c + 1) & 1);
        __syncthreads();
    }

    // ---- neighbor counts: reduce within 16-thread row groups, one atomic each
    int tot_local = 0;
    #pragma unroll
    for (int s = 0; s < 8; ++s) {
        int v = cnt[s];
        v += __shfl_xor_sync(0xffffffffu, v, 1);
        v += __shfl_xor_sync(0xffffffffu, v, 2);
        v += __shfl_xor_sync(0xffffffffu, v, 4);
        v += __shfl_xor_sync(0xffffffffu, v, 8);
        if ((lane & 15) == 0) {
            if (v) atomicAdd(&g_counts[i0 + r_t + 16 * s], v);
            tot_local += v;
        }
    }
    if ((lane & 15) == 0 && tot_local) atomicAdd(&g_total, tot_local);

    // ---- epilogue: fold (hi,lo) adjacent n columns, write split partials
    #pragma unroll
    for (int mt = 0; mt < 2; ++mt) {
        int ibase = i0 + warp_m * 32 + mt * 16 + (lane >> 2);
        #pragma unroll
        for (int g = 0; g < 4; ++g) {
            #pragma unroll
            for (int t = 0; t < 2; ++t) {
                int m_out = warp_n * 32 + g * 8 + t * 4 + (lane & 3);
                const float* cfr = acc[mt][2 * g + t];
                g_Dpart[split][ibase][m_out]     = cfr[0] + cfr[1];
                g_Dpart[split][ibase + 8][m_out] = cfr[2] + cfr[3];
            }
        }
    }
}

// ---------------- kernel 3: combine splits + analytic softmax scale ----------------
__global__ void finalize_kernel(const float* __restrict__ hidden,
                                float* __restrict__ out) {
    int idx4 = (blockIdx.x * NT + threadIdx.x) * 4;
    if (idx4 >= P * MOUT) return;
    if (g_total > 0) {
        int i = idx4 >> 6;
        float cnt = (float)g_counts[i];
        float inv = 1.0f / (cnt + ((float)P - cnt) * expf(-1.000001f));
        float4 s = *reinterpret_cast<const float4*>(&g_Dpart[0][0][0] + idx4);
        #pragma unroll
        for (int sp = 1; sp < SPLITS; ++sp) {
            float4 t = *reinterpret_cast<const float4*>(&g_Dpart[sp][0][0] + idx4);
            s.x += t.x; s.y += t.y; s.z += t.z; s.w += t.w;
        }
        s.x *= inv; s.y *= inv; s.z *= inv; s.w *= inv;
        *reinterpret_cast<float4*>(out + idx4) = s;
    } else {
        *reinterpret_cast<float4*>(out + idx4) =
            *reinterpret_cast<const float4*>(hidden + idx4);
    }
}

// ---------------- launch ----------------
extern "C" void kernel_launch(void* const* d_in, const int* in_sizes, int n_in,
                              void* d_out, int out_size) {
    const float* hidden = (const float*)d_in[0];
    // d_in[1] (corr_index) is unused by the reference math — never read.
    const int*   nei    = (const int*)d_in[2];
    float*       out    = (float*)d_out;

    const int smem_bytes = 65536;   // 2 x (16K A + 16K B)
    cudaFuncSetAttribute(gemm_kernel,
                         cudaFuncAttributeMaxDynamicSharedMemorySize, smem_bytes);

    prep_kernel<<<P / NT, NT>>>(hidden);                              // 16 CTAs
    gemm_kernel<<<dim3(SPLITS, P / ITILE), NT, smem_bytes>>>(nei);    // 128 CTAs
    finalize_kernel<<<(P * MOUT / 4 + NT - 1) / NT, NT>>>(hidden, out);
}

// round 6
// speedup vs baseline: 4.2664x; 1.0576x over previous
#include <cuda_runtime.h>
#include <cuda_bf16.h>
#include <cstdint>

#define P       4096
#define MOUT    64
#define ITILE   128              // i-rows per CTA
#define SPLITS  4
#define KSPLIT  (P / SPLITS)     // 1024
#define KC      128              // k per chunk (256 B/row in smem)
#define NCHUNK  (KSPLIT / KC)    // 8
#define NT      256

// ---------------- device scratch (no allocations allowed) ----------------
__device__ __nv_bfloat16 g_B[128 * P];                // [n][k] bf16, hi/lo interleaved on n
__device__ float         g_Dpart[SPLITS][P][MOUT];    // split-K partials (4 MB)
__device__ int           g_cnt[SPLITS][P];            // per-split row counts (plain stores)
__device__ int           g_total;                     // zero-init at load; atomicOr(1) only

// ---------------- helpers ----------------
__device__ __forceinline__ uint32_t smem_u32(const void* p) {
    uint32_t a;
    asm("{ .reg .u64 t; cvta.to.shared.u64 t, %1; cvt.u32.u64 %0, t; }" : "=r"(a) : "l"(p));
    return a;
}
// Row = 128 bf16 = 256 B = 16 x 16B chunks. chunk' = chunk ^ (row&7):
// 8 consecutive rows at fixed kb hit 8 distinct bank groups -> ldmatrix conflict-free.
__device__ __forceinline__ uint32_t sw2(int row, int kbyte) {
    return (uint32_t)(row * 256) + (uint32_t)((((kbyte >> 4) ^ (row & 7)) << 4) | (kbyte & 15));
}
__device__ __forceinline__ void sts64(uint32_t addr, uint32_t x, uint32_t y) {
    asm volatile("st.shared.v2.b32 [%0], {%1, %2};" :: "r"(addr), "r"(x), "r"(y) : "memory");
}
__device__ __forceinline__ void cp16(uint32_t dst, const void* src) {
    asm volatile("cp.async.cg.shared.global [%0], [%1], 16;" :: "r"(dst), "l"(src) : "memory");
}
#define CP_COMMIT() asm volatile("cp.async.commit_group;" ::: "memory")
#define CP_WAIT0()  asm volatile("cp.async.wait_group 0;" ::: "memory")
__device__ __forceinline__ void ldsm4(uint32_t* r, uint32_t addr) {
    asm volatile("ldmatrix.sync.aligned.m8n8.x4.shared.b16 {%0,%1,%2,%3}, [%4];"
                 : "=r"(r[0]), "=r"(r[1]), "=r"(r[2]), "=r"(r[3]) : "r"(addr));
}
__device__ __forceinline__ void mma16816(float* c, const uint32_t* a, const uint32_t* b) {
    asm volatile("mma.sync.aligned.m16n8k16.row.col.f32.bf16.bf16.f32 "
                 "{%0,%1,%2,%3}, {%4,%5,%6,%7}, {%8,%9}, {%0,%1,%2,%3};"
                 : "+f"(c[0]), "+f"(c[1]), "+f"(c[2]), "+f"(c[3])
                 : "r"(a[0]), "r"(a[1]), "r"(a[2]), "r"(a[3]), "r"(b[0]), "r"(b[1]));
}
__device__ __forceinline__ uint32_t pack_bf16(__nv_bfloat16 a, __nv_bfloat16 b) {
    __nv_bfloat162 t(a, b);
    return *reinterpret_cast<uint32_t*>(&t);
}

// ---------------- kernel 1: build B (hi/lo interleaved on n), coalesced ----------------
__global__ void prep_kernel(const float* __restrict__ hidden) {
    __shared__ float sh[64][68];                       // 64 k-rows x 64 m (padded)
    const int tid = threadIdx.x;
    const int k0  = blockIdx.x * 64;

    #pragma unroll
    for (int q = 0; q < 4; ++q) {                      // load 64x64 fp32, coalesced
        int idx = q * NT + tid;
        int kr = idx >> 4, mc = (idx & 15) * 4;
        float4 v = *reinterpret_cast<const float4*>(hidden + (size_t)(k0 + kr) * MOUT + mc);
        sh[kr][mc] = v.x; sh[kr][mc+1] = v.y; sh[kr][mc+2] = v.z; sh[kr][mc+3] = v.w;
    }
    __syncthreads();

    #pragma unroll
    for (int q = 0; q < 8; ++q) {                      // 128 n x 16 k-quads
        int idx = q * NT + tid;
        int n = idx >> 4, kq = idx & 15;
        int m = n >> 1;
        bool want_lo = n & 1;
        __nv_bfloat16 o[4];
        #pragma unroll
        for (int e = 0; e < 4; ++e) {
            float f = sh[kq * 4 + e][m];
            __nv_bfloat16 hi = __float2bfloat16(f);
            o[e] = want_lo ? __float2bfloat16(f - __bfloat162float(hi)) : hi;
        }
        uint2 pk = make_uint2(pack_bf16(o[0], o[1]), pack_bf16(o[2], o[3]));
        *reinterpret_cast<uint2*>(&g_B[(size_t)n * P + k0 + kq * 4]) = pk;  // 128B/half-warp
    }
}

// ---------------- kernel 2: mma.sync GEMM, mask converted on the fly ----------------
extern __shared__ __align__(16) char smem[];   // [A0 32K][A1 32K][B0 32K][B1 32K]

__global__ __launch_bounds__(NT)
void gemm_kernel(const int* __restrict__ nei) {
    const int tid    = threadIdx.x;
    const int lane   = tid & 31;
    const int w      = tid >> 5;
    const int warp_m = w & 3;        // i-offset = warp_m*32
    const int warp_n = w >> 2;       // n-offset = warp_n*64
    const int split  = blockIdx.x;
    const int i0     = blockIdx.y * ITILE;
    const int k0base = split * KSPLIT;

    const uint32_t sbase = smem_u32(smem);
    const uint32_t sA[2] = {sbase,         sbase + 32768};
    const uint32_t sB[2] = {sbase + 65536, sbase + 98304};

    // A-load mapping: warp w owns rows w + 8s (s=0..15); lane owns k-slice lane*4..lane*4+3
    const int kl = lane * 4;

    float acc[2][8][4];
    #pragma unroll
    for (int a = 0; a < 2; ++a)
        #pragma unroll
        for (int b = 0; b < 8; ++b)
            #pragma unroll
            for (int c = 0; c < 4; ++c) acc[a][b][c] = 0.0f;
    int cnt[16];
    #pragma unroll
    for (int s = 0; s < 16; ++s) cnt[s] = 0;

    int4 va[16];

    auto fill_B = [&](int c, int b) {                  // cp.async gmem->smem, swizzled
        const int k0 = k0base + c * KC;
        const char* gsrc = reinterpret_cast<const char*>(g_B) + (size_t)k0 * 2;
        #pragma unroll
        for (int q = 0; q < 8; ++q) {
            int idx = q * NT + tid;
            int n = idx >> 4, ch = idx & 15;
            cp16(sB[b] + n * 256 + ((ch ^ (n & 7)) << 4),
                 gsrc + (size_t)n * (P * 2) + ch * 16);
        }
    };
    auto load_A = [&](int c) {
        const int k0 = k0base + c * KC;
        #pragma unroll
        for (int s = 0; s < 16; ++s) {
            int row = w + 8 * s;
            va[s] = *reinterpret_cast<const int4*>(nei + (size_t)(i0 + row) * P + k0 + kl);
        }
    };
    auto sts_A = [&](int b) {
        #pragma unroll
        for (int s = 0; s < 16; ++s) {
            int row = w + 8 * s;
            uint32_t e0 = (va[s].x > 0) ? 0x3F80u : 0u;
            uint32_t e1 = (va[s].y > 0) ? 0x3F80u : 0u;
            uint32_t e2 = (va[s].z > 0) ? 0x3F80u : 0u;
            uint32_t e3 = (va[s].w > 0) ? 0x3F80u : 0u;
            cnt[s] += (va[s].x > 0) + (va[s].y > 0) + (va[s].z > 0) + (va[s].w > 0);
            sts64(sA[b] + sw2(row, kl * 2), e0 | (e1 << 16), e2 | (e3 << 16));
        }
    };

    // ---- prolog
    fill_B(0, 0); CP_COMMIT();
    load_A(0);
    sts_A(0);
    CP_WAIT0();
    __syncthreads();

    // ---- pipeline: [cp.async B(c+1) + LDG A(c+1)] -> MMA(c) -> STS A(c+1) -> sync
    #pragma unroll 1
    for (int c = 0; c < NCHUNK; ++c) {
        const int b  = c & 1;
        const int nb = b ^ 1;
        if (c + 1 < NCHUNK) { fill_B(c + 1, nb); CP_COMMIT(); load_A(c + 1); }

        #pragma unroll
        for (int k16 = 0; k16 < KC / 16; ++k16) {
            uint32_t afr[2][4];
            #pragma unroll
            for (int mt = 0; mt < 2; ++mt) {
                int row = warp_m * 32 + mt * 16 + (lane & 15);
                int kb  = k16 * 32 + ((lane >> 4) << 4);
                ldsm4(afr[mt], sA[b] + sw2(row, kb));
            }
            uint32_t bfr[4][4];
            #pragma unroll
            for (int g = 0; g < 4; ++g) {
                int row = warp_n * 64 + g * 16 + (lane & 7) + ((lane >> 4) << 3);
                int kb  = k16 * 32 + (((lane >> 3) & 1) << 4);
                ldsm4(bfr[g], sB[b] + sw2(row, kb));
            }
            #pragma unroll
            for (int mt = 0; mt < 2; ++mt)
                #pragma unroll
                for (int g = 0; g < 4; ++g) {
                    mma16816(acc[mt][2 * g],     afr[mt], &bfr[g][0]);
                    mma16816(acc[mt][2 * g + 1], afr[mt], &bfr[g][2]);
                }
        }

        if (c + 1 < NCHUNK) sts_A(nb);
        CP_WAIT0();
        __syncthreads();
    }

    // ---- counts: warp-wide reduce per owned row, plain stores (exclusive ownership)
    int any = 0;
    #pragma unroll
    for (int s = 0; s < 16; ++s) {
        int v = __reduce_add_sync(0xffffffffu, cnt[s]);
        if (lane == 0) g_cnt[split][i0 + w + 8 * s] = v;
        any |= v;
    }
    if (lane == 0 && any) atomicOr(&g_total, 1);   // idempotent -> graph-replay safe

    // ---- epilogue: fold (hi,lo) adjacent n columns, write split partials
    #pragma unroll
    for (int mt = 0; mt < 2; ++mt) {
        int ibase = i0 + warp_m * 32 + mt * 16 + (lane >> 2);
        #pragma unroll
        for (int g = 0; g < 4; ++g) {
            #pragma unroll
            for (int t = 0; t < 2; ++t) {
                int m_out = warp_n * 32 + g * 8 + t * 4 + (lane & 3);
                const float* cfr = acc[mt][2 * g + t];
                g_Dpart[split][ibase][m_out]     = cfr[0] + cfr[1];
                g_Dpart[split][ibase + 8][m_out] = cfr[2] + cfr[3];
            }
        }
    }
}

// ---------------- kernel 3: combine splits + analytic softmax scale ----------------
__global__ void finalize_kernel(const float* __restrict__ hidden,
                                float* __restrict__ out) {
    int idx4 = (blockIdx.x * NT + threadIdx.x) * 4;
    if (idx4 >= P * MOUT) return;
    if (g_total > 0) {
        int i = idx4 >> 6;
        float cnt = (float)(g_cnt[0][i] + g_cnt[1][i] + g_cnt[2][i] + g_cnt[3][i]);
        float inv = 1.0f / (cnt + ((float)P - cnt) * expf(-1.000001f));
        float4 s = *reinterpret_cast<const float4*>(&g_Dpart[0][0][0] + idx4);
        #pragma unroll
        for (int sp = 1; sp < SPLITS; ++sp) {
            float4 t = *reinterpret_cast<const float4*>(&g_Dpart[sp][0][0] + idx4);
            s.x += t.x; s.y += t.y; s.z += t.z; s.w += t.w;
        }
        s.x *= inv; s.y *= inv; s.z *= inv; s.w *= inv;
        *reinterpret_cast<float4*>(out + idx4) = s;
    } else {
        *reinterpret_cast<float4*>(out + idx4) =
            *reinterpret_cast<const float4*>(hidden + idx4);
    }
}

// ---------------- launch ----------------
extern "C" void kernel_launch(void* const* d_in, const int* in_sizes, int n_in,
                              void* d_out, int out_size) {
    const float* hidden = (const float*)d_in[0];
    // d_in[1] (corr_index) is unused by the reference math — never read.
    const int*   nei    = (const int*)d_in[2];
    float*       out    = (float*)d_out;

    const int smem_bytes = 131072;   // 2 x (32K A + 32K B)
    cudaFuncSetAttribute(gemm_kernel,
                         cudaFuncAttributeMaxDynamicSharedMemorySize, smem_bytes);

    prep_kernel<<<P / 64, NT>>>(hidden);                              // 64 CTAs
    gemm_kernel<<<dim3(SPLITS, P / ITILE), NT, smem_bytes>>>(nei);    // 128 CTAs
    finalize_kernel<<<(P * MOUT / 4 + NT - 1) / NT, NT>>>(hidden, out);
}